// round 1
// baseline (speedup 1.0000x reference)
#include <cuda_runtime.h>
#include <cuda_bf16.h>
#include <cstdint>

#define T_STEPS 2048
#define BATCH   16
#define DIM     1024
#define NDIM    64
#define NTOT    256   // k|v|q|a concatenated

// Scratch (static __device__ globals: allowed, no runtime allocation)
__device__ float g_Bt[DIM * NTOT];               // [DIM][256] combined transposed weights
__device__ float g_P[T_STEPS * BATCH * NTOT];    // projections [t][b][g*64+n]

// ---------------- packed f32x2 helpers (sm_100+) ----------------
__device__ __forceinline__ unsigned long long pack2(float lo, float hi) {
    unsigned long long r;
    asm("mov.b64 %0, {%1, %2};" : "=l"(r) : "f"(lo), "f"(hi));
    return r;
}
__device__ __forceinline__ void unpack2(unsigned long long v, float& lo, float& hi) {
    asm("mov.b64 {%0, %1}, %2;" : "=f"(lo), "=f"(hi) : "l"(v));
}
__device__ __forceinline__ void fma2(unsigned long long& d, unsigned long long a, unsigned long long b) {
    asm("fma.rn.f32x2 %0, %1, %2, %0;" : "+l"(d) : "l"(a), "l"(b));
}

// ---------------- weight prep: Bt[d][g*64+r] = W_g[r][d] ----------------
__global__ void prep_weights(const float* __restrict__ Wk, const float* __restrict__ Wv,
                             const float* __restrict__ Wq, const float* __restrict__ Wa) {
    int d = blockIdx.x;          // 0..1023
    int n = threadIdx.x;         // 0..255
    int g = n >> 6, r = n & 63;
    const float* W = (g == 0) ? Wk : (g == 1) ? Wv : (g == 2) ? Wq : Wa;
    g_Bt[d * NTOT + n] = W[r * DIM + d];
}

// ---------------- projection GEMM: g_P = x[32768,1024] @ g_Bt[1024,256] ----------------
#define BM 128
#define BN 128
#define BK 8

__global__ __launch_bounds__(256) void gemm_proj(const float* __restrict__ A) {
    __shared__ float As[BK][BM];
    __shared__ float Bs[BK][BN];
    const int n0 = blockIdx.x * BN;
    const int m0 = blockIdx.y * BM;
    const int tid = threadIdx.x;
    const int tx = tid & 15;       // 16 in N dir
    const int ty = tid >> 4;       // 16 in M dir

    unsigned long long acc[8][4];  // 8 rows x 4 packed (2-wide) cols
    #pragma unroll
    for (int i = 0; i < 8; i++)
        #pragma unroll
        for (int j = 0; j < 4; j++) acc[i][j] = 0ULL;   // bits of (+0.f, +0.f)

    const int am = tid >> 1;            // 0..127
    const int ak = (tid & 1) * 4;       // 0 or 4
    const int bk = tid >> 5;            // 0..7
    const int bn = (tid & 31) * 4;      // 0..124

    for (int k0 = 0; k0 < DIM; k0 += BK) {
        float4 av = *(const float4*)&A[(size_t)(m0 + am) * DIM + k0 + ak];
        As[ak + 0][am] = av.x; As[ak + 1][am] = av.y;
        As[ak + 2][am] = av.z; As[ak + 3][am] = av.w;
        float4 bv = *(const float4*)&g_Bt[(size_t)(k0 + bk) * NTOT + n0 + bn];
        *(float4*)&Bs[bk][bn] = bv;
        __syncthreads();

        #pragma unroll
        for (int kk = 0; kk < BK; kk++) {
            float4 a0 = *(const float4*)&As[kk][ty * 8];
            float4 a1 = *(const float4*)&As[kk][ty * 8 + 4];
            const unsigned long long* bp =
                (const unsigned long long*)&Bs[kk][tx * 8];
            unsigned long long b2[4];
            #pragma unroll
            for (int j = 0; j < 4; j++) b2[j] = bp[j];
            float af[8] = {a0.x, a0.y, a0.z, a0.w, a1.x, a1.y, a1.z, a1.w};
            #pragma unroll
            for (int i = 0; i < 8; i++) {
                unsigned long long a2 = pack2(af[i], af[i]);
                #pragma unroll
                for (int j = 0; j < 4; j++) fma2(acc[i][j], a2, b2[j]);
            }
        }
        __syncthreads();
    }

    #pragma unroll
    for (int i = 0; i < 8; i++) {
        size_t row = (size_t)(m0 + ty * 8 + i);
        #pragma unroll
        for (int j = 0; j < 4; j++)
            *(unsigned long long*)&g_P[row * NTOT + n0 + tx * 8 + 2 * j] = acc[i][j];
    }
}

// ---------------- recurrence: one block per batch, S in registers ----------------
// thread layout: row = tid/4 (0..63), c = tid%4 owns cols [c*16, c*16+16)
__global__ __launch_bounds__(256) void recur(const float* __restrict__ S0,
                                             const float* __restrict__ dalpha,
                                             const float* __restrict__ balpha,
                                             float* __restrict__ out,
                                             float* __restrict__ Sfinal) {
    const int b = blockIdx.x;
    const int tid = threadIdx.x;
    const int row = tid >> 2;
    const int c = tid & 3;
    __shared__ __align__(16) float sh[2][NTOT];

    float S[16];
    #pragma unroll
    for (int j = 0; j < 16; j++)
        S[j] = S0[((size_t)b * NDIM + row) * NDIM + c * 16 + j];

    const float da = dalpha[row];
    const float ba = balpha[row];

    sh[0][tid] = g_P[(size_t)(0 * BATCH + b) * NTOT + tid];
    __syncthreads();

    for (int t = 0; t < T_STEPS; ++t) {
        const int buf = t & 1;
        float pf = 0.f;
        if (t + 1 < T_STEPS)
            pf = g_P[((size_t)(t + 1) * BATCH + b) * NTOT + tid];

        const float* kv = sh[buf];
        float k[16], q[16];
        #pragma unroll
        for (int j4 = 0; j4 < 4; j4++) {
            float4 kk4 = *(const float4*)&kv[c * 16 + 4 * j4];
            float4 qq4 = *(const float4*)&kv[2 * NDIM + c * 16 + 4 * j4];
            k[4 * j4 + 0] = kk4.x; k[4 * j4 + 1] = kk4.y;
            k[4 * j4 + 2] = kk4.z; k[4 * j4 + 3] = kk4.w;
            q[4 * j4 + 0] = qq4.x; q[4 * j4 + 1] = qq4.y;
            q[4 * j4 + 2] = qq4.z; q[4 * j4 + 3] = qq4.w;
        }

        // r1 = (S@k) partial, r2 = (S@q) partial, kq = (k.q) partial over this chunk
        float r1a = 0.f, r1b = 0.f, r2a = 0.f, r2b = 0.f, kqa = 0.f, kqb = 0.f;
        #pragma unroll
        for (int j = 0; j < 16; j += 2) {
            r1a = fmaf(S[j], k[j], r1a);       r1b = fmaf(S[j + 1], k[j + 1], r1b);
            r2a = fmaf(S[j], q[j], r2a);       r2b = fmaf(S[j + 1], q[j + 1], r2b);
            kqa = fmaf(k[j], q[j], kqa);       kqb = fmaf(k[j + 1], q[j + 1], kqb);
        }
        float r1 = r1a + r1b, r2 = r2a + r2b, kq = kqa + kqb;
        // reduce over the 4 column-chunk lanes of this row
        r1 += __shfl_xor_sync(0xffffffffu, r1, 1);
        r1 += __shfl_xor_sync(0xffffffffu, r1, 2);
        r2 += __shfl_xor_sync(0xffffffffu, r2, 1);
        r2 += __shfl_xor_sync(0xffffffffu, r2, 2);
        kq += __shfl_xor_sync(0xffffffffu, kq, 1);
        kq += __shfl_xor_sync(0xffffffffu, kq, 2);

        const float vi = kv[NDIM + row];        // v[row]
        const float ax = kv[3 * NDIM + row];    // a[row]
        const float z = fmaf(da, r1, ax + ba);
        const float alpha = 1.0f / (1.0f + __expf(-z));
        const float w = (1.0f - alpha) * vi;

        #pragma unroll
        for (int j = 0; j < 16; j++)
            S[j] = fmaf(alpha, S[j], w * k[j]);

        if (c == 0) {
            // out_i = sum_j S_new[i][j] q[j] = alpha*r2 + w*kq ; y = out * silu(out)
            float o = fmaf(alpha, r2, w * kq);
            float sg = 1.0f / (1.0f + __expf(-o));
            out[((size_t)t * BATCH + b) * NDIM + row] = o * o * sg;
        }

        sh[buf ^ 1][tid] = pf;
        __syncthreads();
    }

    if (Sfinal != nullptr) {
        #pragma unroll
        for (int j = 0; j < 16; j++)
            Sfinal[((size_t)b * NDIM + row) * NDIM + c * 16 + j] = S[j];
    }
}

// ---------------- launch ----------------
extern "C" void kernel_launch(void* const* d_in, const int* in_sizes, int n_in,
                              void* d_out, int out_size) {
    const float* x  = (const float*)d_in[0];
    const float* S0 = (const float*)d_in[1];
    const float* Wk = (const float*)d_in[2];
    const float* Wv = (const float*)d_in[3];
    const float* Wq = (const float*)d_in[4];
    const float* Wa = (const float*)d_in[5];
    const float* da = (const float*)d_in[6];
    const float* ba = (const float*)d_in[7];

    float* out = (float*)d_out;
    const int out_elems = T_STEPS * BATCH * NDIM;          // 2097152
    const int sf_elems  = BATCH * NDIM * NDIM;             // 65536
    float* Sf = (out_size >= out_elems + sf_elems) ? (out + out_elems) : nullptr;

    prep_weights<<<DIM, NTOT>>>(Wk, Wv, Wq, Wa);

    dim3 ggrid(NTOT / BN, (T_STEPS * BATCH) / BM);         // (2, 256)
    gemm_proj<<<ggrid, 256>>>(x);

    recur<<<BATCH, 256>>>(S0, da, ba, out, Sf);
}

// round 2
// speedup vs baseline: 1.1651x; 1.1651x over previous
#include <cuda_runtime.h>
#include <cuda_bf16.h>
#include <cstdint>

#define T_STEPS 2048
#define BATCH   16
#define DIM     1024
#define NDIM    64
#define NTOT    256
#define MROWS   (T_STEPS * BATCH)   // 32768

// ---------------- static device scratch ----------------
__device__ __nv_bfloat16 g_Ah[MROWS * DIM];   // x hi
__device__ __nv_bfloat16 g_Al[MROWS * DIM];   // x lo
__device__ __nv_bfloat16 g_Bh[NTOT * DIM];    // weights hi, [n][k]
__device__ __nv_bfloat16 g_Bl[NTOT * DIM];    // weights lo
__device__ float g_P[MROWS * NTOT];           // projections [t*B+b][k|v|q|a]

// ---------------- PTX helpers ----------------
__device__ __forceinline__ uint32_t smem_u32(const void* p) {
    return (uint32_t)__cvta_generic_to_shared(p);
}
__device__ __forceinline__ void cpa16(uint32_t sa, const void* g) {
    asm volatile("cp.async.cg.shared.global [%0], [%1], 16;" :: "r"(sa), "l"(g) : "memory");
}
__device__ __forceinline__ void cp_commit() {
    asm volatile("cp.async.commit_group;" ::: "memory");
}
template<int N>
__device__ __forceinline__ void cp_wait() {
    asm volatile("cp.async.wait_group %0;" :: "n"(N) : "memory");
}
__device__ __forceinline__ void ldm_x4(uint32_t& r0, uint32_t& r1, uint32_t& r2, uint32_t& r3,
                                       uint32_t addr) {
    asm volatile("ldmatrix.sync.aligned.m8n8.x4.shared.b16 {%0,%1,%2,%3}, [%4];"
                 : "=r"(r0), "=r"(r1), "=r"(r2), "=r"(r3) : "r"(addr));
}
__device__ __forceinline__ void mma_bf16(float* c, const uint32_t* a, const uint32_t* b) {
    asm volatile("mma.sync.aligned.m16n8k16.row.col.f32.bf16.bf16.f32 "
                 "{%0,%1,%2,%3}, {%4,%5,%6,%7}, {%8,%9}, {%0,%1,%2,%3};"
                 : "+f"(c[0]), "+f"(c[1]), "+f"(c[2]), "+f"(c[3])
                 : "r"(a[0]), "r"(a[1]), "r"(a[2]), "r"(a[3]), "r"(b[0]), "r"(b[1]));
}
__device__ __forceinline__ void split_bf16(float x, __nv_bfloat16& h, __nv_bfloat16& l) {
    h = __float2bfloat16(x);
    l = __float2bfloat16(x - __bfloat162float(h));
}

// ---------------- prep: fp32 -> bf16 hi/lo ----------------
__global__ void convert_x(const float* __restrict__ x) {
    const int total4 = MROWS * DIM / 4;
    for (int i = blockIdx.x * blockDim.x + threadIdx.x; i < total4;
         i += gridDim.x * blockDim.x) {
        float4 v = ((const float4*)x)[i];
        __nv_bfloat16 h0, h1, h2, h3, l0, l1, l2, l3;
        split_bf16(v.x, h0, l0); split_bf16(v.y, h1, l1);
        split_bf16(v.z, h2, l2); split_bf16(v.w, h3, l3);
        ((__nv_bfloat162*)g_Ah)[2 * i + 0] = __nv_bfloat162(h0, h1);
        ((__nv_bfloat162*)g_Ah)[2 * i + 1] = __nv_bfloat162(h2, h3);
        ((__nv_bfloat162*)g_Al)[2 * i + 0] = __nv_bfloat162(l0, l1);
        ((__nv_bfloat162*)g_Al)[2 * i + 1] = __nv_bfloat162(l2, l3);
    }
}

__global__ void convert_w(const float* __restrict__ Wk, const float* __restrict__ Wv,
                          const float* __restrict__ Wq, const float* __restrict__ Wa) {
    int n = blockIdx.x;            // 0..255
    int g = n >> 6, r = n & 63;
    const float* W = (g == 0) ? Wk : (g == 1) ? Wv : (g == 2) ? Wq : Wa;
    for (int d = threadIdx.x; d < DIM; d += blockDim.x) {
        __nv_bfloat16 h, l;
        split_bf16(W[r * DIM + d], h, l);
        g_Bh[n * DIM + d] = h;
        g_Bl[n * DIM + d] = l;
    }
}

// ---------------- tensor-core projection GEMM ----------------
// C[32768, 256] = A[32768,1024] x B[n][k]^T   (bf16 split: hi*hi + hi*lo + lo*hi)
#define BM 128
#define BN 128
#define BK 32
#define LDP 40                       // padded row (elements); 80B row stride
#define KT (DIM / BK)                // 32

// smem element offset: [stage][arr(Ah,Al,Bh,Bl)][row 0..127][col 0..39]
__device__ __forceinline__ uint32_t soff(int stage, int arr, int row, int col) {
    return (uint32_t)((((stage * 4 + arr) * 128 + row) * LDP + col) * 2);
}

__global__ __launch_bounds__(256, 1) void gemm_mma(int m_blocks_y) {
    extern __shared__ __nv_bfloat16 smem[];
    const uint32_t sbase = smem_u32(smem);

    const int m0 = blockIdx.y * BM;
    const int n0 = blockIdx.x * BN;
    const int tid = threadIdx.x;
    const int wid = tid >> 5;
    const int lane = tid & 31;
    const int warp_m = (wid & 3) * 32;    // 4 warps along M
    const int warp_n = (wid >> 2) * 64;   // 2 warps along N

    float acc[2][8][4];
    #pragma unroll
    for (int i = 0; i < 2; i++)
        #pragma unroll
        for (int j = 0; j < 8; j++)
            #pragma unroll
            for (int r = 0; r < 4; r++) acc[i][j][r] = 0.f;

    // ldmatrix lane address components
    const int lm = lane >> 3;                         // which 8x8 matrix
    const int arow = (lm & 1) * 8 + (lane & 7);       // A: row offset
    const int akc  = (lm >> 1) * 8;                   // A: k offset
    const int bnof = (lm >> 1) * 8 + (lane & 7);      // B: n offset
    const int bkc  = (lm & 1) * 8;                    // B: k offset

    // stage loader: 8 x 16B cp.async per thread
    auto load_stage = [&](int stage, int k0) {
        #pragma unroll
        for (int arr = 0; arr < 4; arr++) {
            const __nv_bfloat16* gb = (arr == 0) ? g_Ah : (arr == 1) ? g_Al
                                   : (arr == 2) ? g_Bh : g_Bl;
            const int rbase = (arr < 2) ? m0 : n0;
            #pragma unroll
            for (int h = 0; h < 2; h++) {
                int cl = h * 256 + tid;
                int row = cl >> 2;
                int seg = cl & 3;
                cpa16(sbase + soff(stage, arr, row, seg * 8),
                      gb + (size_t)(rbase + row) * DIM + k0 + seg * 8);
            }
        }
    };

    load_stage(0, 0);
    cp_commit();

    for (int kt = 0; kt < KT; ++kt) {
        const int cur = kt & 1;
        if (kt + 1 < KT) {
            load_stage((kt + 1) & 1, (kt + 1) * BK);
            cp_commit();
            cp_wait<1>();
        } else {
            cp_wait<0>();
        }
        __syncthreads();

        #pragma unroll
        for (int kk = 0; kk < BK; kk += 16) {
            uint32_t ah[2][4], al[2][4], bh[8][2], bl[8][2];
            #pragma unroll
            for (int mi = 0; mi < 2; mi++) {
                ldm_x4(ah[mi][0], ah[mi][1], ah[mi][2], ah[mi][3],
                       sbase + soff(cur, 0, warp_m + mi * 16 + arow, kk + akc));
                ldm_x4(al[mi][0], al[mi][1], al[mi][2], al[mi][3],
                       sbase + soff(cur, 1, warp_m + mi * 16 + arow, kk + akc));
            }
            #pragma unroll
            for (int p = 0; p < 4; p++) {
                ldm_x4(bh[2 * p][0], bh[2 * p][1], bh[2 * p + 1][0], bh[2 * p + 1][1],
                       sbase + soff(cur, 2, warp_n + p * 16 + bnof, kk + bkc));
                ldm_x4(bl[2 * p][0], bl[2 * p][1], bl[2 * p + 1][0], bl[2 * p + 1][1],
                       sbase + soff(cur, 3, warp_n + p * 16 + bnof, kk + bkc));
            }
            #pragma unroll
            for (int mi = 0; mi < 2; mi++)
                #pragma unroll
                for (int nb = 0; nb < 8; nb++) {
                    mma_bf16(acc[mi][nb], ah[mi], bh[nb]);
                    mma_bf16(acc[mi][nb], ah[mi], bl[nb]);
                    mma_bf16(acc[mi][nb], al[mi], bh[nb]);
                }
        }
        __syncthreads();
    }

    // epilogue: c0,c1 -> row l>>2; c2,c3 -> row (l>>2)+8; cols 2*(l&3)
    const int cr = lane >> 2;
    const int cc = (lane & 3) * 2;
    #pragma unroll
    for (int mi = 0; mi < 2; mi++) {
        #pragma unroll
        for (int nb = 0; nb < 8; nb++) {
            int row = m0 + warp_m + mi * 16 + cr;
            int col = n0 + warp_n + nb * 8 + cc;
            *(float2*)&g_P[(size_t)row * NTOT + col] =
                make_float2(acc[mi][nb][0], acc[mi][nb][1]);
            *(float2*)&g_P[(size_t)(row + 8) * NTOT + col] =
                make_float2(acc[mi][nb][2], acc[mi][nb][3]);
        }
    }
}

// ---------------- recurrence: one block per batch, S in registers ----------------
__global__ __launch_bounds__(256) void recur(const float* __restrict__ S0,
                                             const float* __restrict__ dalpha,
                                             const float* __restrict__ balpha,
                                             float* __restrict__ out,
                                             float* __restrict__ Sfinal) {
    const int b = blockIdx.x;
    const int tid = threadIdx.x;
    const int row = tid >> 2;
    const int c = tid & 3;
    __shared__ __align__(16) float sh[2][NTOT];

    float S[16];
    #pragma unroll
    for (int j = 0; j < 16; j++)
        S[j] = S0[((size_t)b * NDIM + row) * NDIM + c * 16 + j];

    const float da = dalpha[row];
    const float ba = balpha[row];

    sh[0][tid] = g_P[(size_t)(0 * BATCH + b) * NTOT + tid];
    __syncthreads();

    for (int t = 0; t < T_STEPS; ++t) {
        const int buf = t & 1;
        float pf = 0.f;
        if (t + 1 < T_STEPS)
            pf = g_P[((size_t)(t + 1) * BATCH + b) * NTOT + tid];

        const float* kv = sh[buf];
        float k[16], q[16];
        #pragma unroll
        for (int j4 = 0; j4 < 4; j4++) {
            float4 kk4 = *(const float4*)&kv[c * 16 + 4 * j4];
            float4 qq4 = *(const float4*)&kv[2 * NDIM + c * 16 + 4 * j4];
            k[4 * j4 + 0] = kk4.x; k[4 * j4 + 1] = kk4.y;
            k[4 * j4 + 2] = kk4.z; k[4 * j4 + 3] = kk4.w;
            q[4 * j4 + 0] = qq4.x; q[4 * j4 + 1] = qq4.y;
            q[4 * j4 + 2] = qq4.z; q[4 * j4 + 3] = qq4.w;
        }

        float r1a = 0.f, r1b = 0.f, r2a = 0.f, r2b = 0.f, kqa = 0.f, kqb = 0.f;
        #pragma unroll
        for (int j = 0; j < 16; j += 2) {
            r1a = fmaf(S[j], k[j], r1a);       r1b = fmaf(S[j + 1], k[j + 1], r1b);
            r2a = fmaf(S[j], q[j], r2a);       r2b = fmaf(S[j + 1], q[j + 1], r2b);
            kqa = fmaf(k[j], q[j], kqa);       kqb = fmaf(k[j + 1], q[j + 1], kqb);
        }
        float r1 = r1a + r1b, r2 = r2a + r2b, kq = kqa + kqb;
        r1 += __shfl_xor_sync(0xffffffffu, r1, 1);
        r1 += __shfl_xor_sync(0xffffffffu, r1, 2);
        r2 += __shfl_xor_sync(0xffffffffu, r2, 1);
        r2 += __shfl_xor_sync(0xffffffffu, r2, 2);
        kq += __shfl_xor_sync(0xffffffffu, kq, 1);
        kq += __shfl_xor_sync(0xffffffffu, kq, 2);

        const float vi = kv[NDIM + row];
        const float ax = kv[3 * NDIM + row];
        const float z = fmaf(da, r1, ax + ba);
        const float alpha = 1.0f / (1.0f + __expf(-z));
        const float w = (1.0f - alpha) * vi;

        #pragma unroll
        for (int j = 0; j < 16; j++)
            S[j] = fmaf(alpha, S[j], w * k[j]);

        if (c == 0) {
            float o = fmaf(alpha, r2, w * kq);
            float sg = 1.0f / (1.0f + __expf(-o));
            out[((size_t)t * BATCH + b) * NDIM + row] = o * o * sg;
        }

        sh[buf ^ 1][tid] = pf;
        __syncthreads();
    }

    if (Sfinal != nullptr) {
        #pragma unroll
        for (int j = 0; j < 16; j++)
            Sfinal[((size_t)b * NDIM + row) * NDIM + c * 16 + j] = S[j];
    }
}

// ---------------- launch ----------------
extern "C" void kernel_launch(void* const* d_in, const int* in_sizes, int n_in,
                              void* d_out, int out_size) {
    const float* x  = (const float*)d_in[0];
    const float* S0 = (const float*)d_in[1];
    const float* Wk = (const float*)d_in[2];
    const float* Wv = (const float*)d_in[3];
    const float* Wq = (const float*)d_in[4];
    const float* Wa = (const float*)d_in[5];
    const float* da = (const float*)d_in[6];
    const float* ba = (const float*)d_in[7];

    float* out = (float*)d_out;
    const int out_elems = T_STEPS * BATCH * NDIM;
    const int sf_elems  = BATCH * NDIM * NDIM;
    float* Sf = (out_size >= out_elems + sf_elems) ? (out + out_elems) : nullptr;

    const int smem_bytes = 2 * 4 * 128 * LDP * 2;   // 81920
    cudaFuncSetAttribute(gemm_mma, cudaFuncAttributeMaxDynamicSharedMemorySize, smem_bytes);

    convert_x<<<2048, 256>>>(x);
    convert_w<<<NTOT, 256>>>(Wk, Wv, Wq, Wa);

    dim3 ggrid(NTOT / BN, MROWS / BM);   // (2, 256)
    gemm_mma<<<ggrid, 256, smem_bytes>>>(ggrid.y);

    recur<<<BATCH, 256>>>(S0, da, ba, out, Sf);
}

// round 4
// speedup vs baseline: 1.3710x; 1.1767x over previous
#include <cuda_runtime.h>
#include <cuda_bf16.h>
#include <cstdint>

#define T_STEPS 2048
#define BATCH   16
#define DIM     1024
#define NDIM    64
#define NTOT    256
#define MROWS   (T_STEPS * BATCH)   // 32768

// ---------------- static device scratch ----------------
__device__ __nv_bfloat16 g_Ah[MROWS * DIM];
__device__ __nv_bfloat16 g_Al[MROWS * DIM];
__device__ __nv_bfloat16 g_Bh[NTOT * DIM];    // [n][k]
__device__ __nv_bfloat16 g_Bl[NTOT * DIM];
__device__ float g_P[MROWS * NTOT];           // [t*B+b][k|v|q|a]

// ---------------- PTX helpers (baseline ISA only) ----------------
__device__ __forceinline__ uint32_t smem_u32(const void* p) {
    return (uint32_t)__cvta_generic_to_shared(p);
}
__device__ __forceinline__ void cpa16(uint32_t sa, const void* g) {
    asm volatile("cp.async.cg.shared.global [%0], [%1], 16;" :: "r"(sa), "l"(g) : "memory");
}
__device__ __forceinline__ void cp_commit() {
    asm volatile("cp.async.commit_group;" ::: "memory");
}
template<int N>
__device__ __forceinline__ void cp_wait() {
    asm volatile("cp.async.wait_group %0;" :: "n"(N) : "memory");
}
__device__ __forceinline__ void ldm_x4(uint32_t& r0, uint32_t& r1, uint32_t& r2, uint32_t& r3,
                                       uint32_t addr) {
    asm volatile("ldmatrix.sync.aligned.m8n8.x4.shared.b16 {%0,%1,%2,%3}, [%4];"
                 : "=r"(r0), "=r"(r1), "=r"(r2), "=r"(r3) : "r"(addr));
}
__device__ __forceinline__ void mma_bf16(float* c, const uint32_t* a, const uint32_t* b) {
    asm volatile("mma.sync.aligned.m16n8k16.row.col.f32.bf16.bf16.f32 "
                 "{%0,%1,%2,%3}, {%4,%5,%6,%7}, {%8,%9}, {%0,%1,%2,%3};"
                 : "+f"(c[0]), "+f"(c[1]), "+f"(c[2]), "+f"(c[3])
                 : "r"(a[0]), "r"(a[1]), "r"(a[2]), "r"(a[3]), "r"(b[0]), "r"(b[1]));
}

// packed f32x2
typedef unsigned long long ull;
__device__ __forceinline__ ull pack2(float lo, float hi) {
    ull r; asm("mov.b64 %0, {%1, %2};" : "=l"(r) : "f"(lo), "f"(hi)); return r;
}
__device__ __forceinline__ void unpack2(ull v, float& lo, float& hi) {
    asm("mov.b64 {%0, %1}, %2;" : "=f"(lo), "=f"(hi) : "l"(v));
}
__device__ __forceinline__ ull fma2g(ull a, ull b, ull c) {
    ull d; asm("fma.rn.f32x2 %0, %1, %2, %3;" : "=l"(d) : "l"(a), "l"(b), "l"(c)); return d;
}
__device__ __forceinline__ ull mul2(ull a, ull b) {
    ull d; asm("mul.rn.f32x2 %0, %1, %2;" : "=l"(d) : "l"(a), "l"(b)); return d;
}

__device__ __forceinline__ void split_bf16(float x, __nv_bfloat16& h, __nv_bfloat16& l) {
    h = __float2bfloat16(x);
    l = __float2bfloat16(x - __bfloat162float(h));
}

// ---------------- prep kernels ----------------
__global__ void convert_x(const float* __restrict__ x) {
    const int total4 = MROWS * DIM / 4;
    for (int i = blockIdx.x * blockDim.x + threadIdx.x; i < total4;
         i += gridDim.x * blockDim.x) {
        float4 v = ((const float4*)x)[i];
        __nv_bfloat16 h0, h1, h2, h3, l0, l1, l2, l3;
        split_bf16(v.x, h0, l0); split_bf16(v.y, h1, l1);
        split_bf16(v.z, h2, l2); split_bf16(v.w, h3, l3);
        ((__nv_bfloat162*)g_Ah)[2 * i + 0] = __nv_bfloat162(h0, h1);
        ((__nv_bfloat162*)g_Ah)[2 * i + 1] = __nv_bfloat162(h2, h3);
        ((__nv_bfloat162*)g_Al)[2 * i + 0] = __nv_bfloat162(l0, l1);
        ((__nv_bfloat162*)g_Al)[2 * i + 1] = __nv_bfloat162(l2, l3);
    }
}

__global__ void convert_w(const float* __restrict__ Wk, const float* __restrict__ Wv,
                          const float* __restrict__ Wq, const float* __restrict__ Wa) {
    int n = blockIdx.x;
    int g = n >> 6, r = n & 63;
    const float* W = (g == 0) ? Wk : (g == 1) ? Wv : (g == 2) ? Wq : Wa;
    for (int d = threadIdx.x; d < DIM; d += blockDim.x) {
        __nv_bfloat16 h, l;
        split_bf16(W[r * DIM + d], h, l);
        g_Bh[n * DIM + d] = h;
        g_Bl[n * DIM + d] = l;
    }
}

// ---------------- mma.sync GEMM: g_P = A[32768,1024] x B[256,1024]^T, 3-pass bf16 ----------------
#define BM 128
#define BN 128
#define BK 32
#define LDP 40                       // padded row (elements); conflict-free for ldmatrix
#define KT (DIM / BK)                // 32
#define NSTAGE 3
#define STAGE_ELE (4 * 128 * LDP)    // per-stage elements

__device__ __forceinline__ uint32_t soff(int stage, int arr, int row, int col) {
    return (uint32_t)(((stage * STAGE_ELE) + ((arr * 128 + row) * LDP) + col) * 2);
}

__global__ __launch_bounds__(256, 1) void gemm_mma(int unused) {
    extern __shared__ __nv_bfloat16 smem[];
    const uint32_t sbase = smem_u32(smem);

    const int m0 = blockIdx.y * BM;
    const int n0 = blockIdx.x * BN;
    const int tid = threadIdx.x;
    const int wid = tid >> 5;
    const int lane = tid & 31;
    const int warp_m = (wid & 3) * 32;
    const int warp_n = (wid >> 2) * 64;

    float acc[2][8][4];
    #pragma unroll
    for (int i = 0; i < 2; i++)
        #pragma unroll
        for (int j = 0; j < 8; j++)
            #pragma unroll
            for (int r = 0; r < 4; r++) acc[i][j][r] = 0.f;

    const int lm = lane >> 3;
    const int arow = (lm & 1) * 8 + (lane & 7);
    const int akc  = (lm >> 1) * 8;
    const int bnof = (lm >> 1) * 8 + (lane & 7);
    const int bkc  = (lm & 1) * 8;

    auto load_stage = [&](int stage, int kt) {
        const int k0 = kt * BK;
        #pragma unroll
        for (int arr = 0; arr < 4; arr++) {
            const __nv_bfloat16* gb = (arr == 0) ? g_Ah : (arr == 1) ? g_Al
                                   : (arr == 2) ? g_Bh : g_Bl;
            const int rbase = (arr < 2) ? m0 : n0;
            #pragma unroll
            for (int h = 0; h < 2; h++) {
                int cl = h * 256 + tid;
                int row = cl >> 2;
                int seg = cl & 3;
                cpa16(sbase + soff(stage, arr, row, seg * 8),
                      gb + (size_t)(rbase + row) * DIM + k0 + seg * 8);
            }
        }
        cp_commit();
    };

    load_stage(0, 0);
    load_stage(1, 1);

    int cur = 0;
    for (int kt = 0; kt < KT; ++kt) {
        if (kt + 2 < KT) {
            load_stage((kt + 2) % NSTAGE, kt + 2);
            cp_wait<2>();
        } else if (kt + 1 < KT) {
            cp_wait<1>();
        } else {
            cp_wait<0>();
        }
        __syncthreads();

        #pragma unroll
        for (int kk = 0; kk < BK; kk += 16) {
            uint32_t ah[2][4], al[2][4], bh[8][2], bl[8][2];
            #pragma unroll
            for (int mi = 0; mi < 2; mi++) {
                ldm_x4(ah[mi][0], ah[mi][1], ah[mi][2], ah[mi][3],
                       sbase + soff(cur, 0, warp_m + mi * 16 + arow, kk + akc));
                ldm_x4(al[mi][0], al[mi][1], al[mi][2], al[mi][3],
                       sbase + soff(cur, 1, warp_m + mi * 16 + arow, kk + akc));
            }
            #pragma unroll
            for (int p = 0; p < 4; p++) {
                ldm_x4(bh[2 * p][0], bh[2 * p][1], bh[2 * p + 1][0], bh[2 * p + 1][1],
                       sbase + soff(cur, 2, warp_n + p * 16 + bnof, kk + bkc));
                ldm_x4(bl[2 * p][0], bl[2 * p][1], bl[2 * p + 1][0], bl[2 * p + 1][1],
                       sbase + soff(cur, 3, warp_n + p * 16 + bnof, kk + bkc));
            }
            #pragma unroll
            for (int mi = 0; mi < 2; mi++)
                #pragma unroll
                for (int nb = 0; nb < 8; nb++) {
                    mma_bf16(acc[mi][nb], ah[mi], bh[nb]);
                    mma_bf16(acc[mi][nb], ah[mi], bl[nb]);
                    mma_bf16(acc[mi][nb], al[mi], bh[nb]);
                }
        }
        __syncthreads();
        cur = (cur + 1) % NSTAGE;
    }

    const int cr = lane >> 2;
    const int cc = (lane & 3) * 2;
    #pragma unroll
    for (int mi = 0; mi < 2; mi++) {
        #pragma unroll
        for (int nb = 0; nb < 8; nb++) {
            int row = m0 + warp_m + mi * 16 + cr;
            int col = n0 + warp_n + nb * 8 + cc;
            *(float2*)&g_P[(size_t)row * NTOT + col] =
                make_float2(acc[mi][nb][0], acc[mi][nb][1]);
            *(float2*)&g_P[(size_t)(row + 8) * NTOT + col] =
                make_float2(acc[mi][nb][2], acc[mi][nb][3]);
        }
    }
}

// ---------------- recurrence: warp-autonomous + cp.async ring, no syncthreads ----------------
#define RDEPTH 8    // ring stages
#define RDIST  7    // prefetch distance

__global__ __launch_bounds__(32, 1) void recur_w(const float* __restrict__ S0,
                                                 const float* __restrict__ dalpha,
                                                 const float* __restrict__ balpha,
                                                 float* __restrict__ out,
                                                 float* __restrict__ Sfinal) {
    const int b = blockIdx.x >> 3;
    const int rw = (blockIdx.x & 7) * 8;
    const int lane = threadIdx.x;
    const int row = rw + (lane >> 2);
    const int c = lane & 3;

    __shared__ __align__(16) float ring[RDEPTH][NTOT];   // 8KB

    ull S2[8];
    {
        const float* sp = S0 + ((size_t)b * NDIM + row) * NDIM + c * 16;
        #pragma unroll
        for (int j = 0; j < 4; j++) {
            float4 v = *(const float4*)(sp + 4 * j);
            S2[2 * j]     = pack2(v.x, v.y);
            S2[2 * j + 1] = pack2(v.z, v.w);
        }
    }
    const float da = dalpha[row];
    const float ba = balpha[row];

    // prime the ring: stages 0..RDIST-1
    #pragma unroll
    for (int p = 0; p < RDIST; p++) {
        const float* gp = g_P + (size_t)(p * BATCH + b) * NTOT;
        uint32_t sa = smem_u32(&ring[p][lane * 8]);
        cpa16(sa, gp + lane * 8);
        cpa16(sa + 16, gp + lane * 8 + 4);
        cp_commit();
    }

    for (int t = 0; t < T_STEPS; ++t) {
        cp_wait<RDIST - 1>();
        __syncwarp();

        const float* kv = ring[t & (RDEPTH - 1)];
        ull k2[8], q2[8];
        #pragma unroll
        for (int j = 0; j < 4; j++) {
            float4 kk = *(const float4*)&kv[c * 16 + 4 * j];
            float4 qq = *(const float4*)&kv[2 * NDIM + c * 16 + 4 * j];
            k2[2 * j]     = pack2(kk.x, kk.y);
            k2[2 * j + 1] = pack2(kk.z, kk.w);
            q2[2 * j]     = pack2(qq.x, qq.y);
            q2[2 * j + 1] = pack2(qq.z, qq.w);
        }
        const float vv = kv[NDIM + row];
        const float ax = kv[3 * NDIM + row];

        // prefetch stage t+RDIST (slot (t+RDIST)&7 was read at iter t-1)
        {
            const int tp = t + RDIST;
            if (tp < T_STEPS) {
                const float* gp = g_P + (size_t)(tp * BATCH + b) * NTOT;
                uint32_t sa = smem_u32(&ring[tp & (RDEPTH - 1)][lane * 8]);
                cpa16(sa, gp + lane * 8);
                cpa16(sa + 16, gp + lane * 8 + 4);
            }
            cp_commit();
        }

        // dots over this 16-col chunk
        ull a1 = 0, a2 = 0, b1 = 0, b2 = 0, c1 = 0, c2 = 0;
        #pragma unroll
        for (int j = 0; j < 4; j++) {
            a1 = fma2g(S2[2 * j],     k2[2 * j],     a1);
            a2 = fma2g(S2[2 * j + 1], k2[2 * j + 1], a2);
            b1 = fma2g(S2[2 * j],     q2[2 * j],     b1);
            b2 = fma2g(S2[2 * j + 1], q2[2 * j + 1], b2);
            c1 = fma2g(k2[2 * j],     q2[2 * j],     c1);
            c2 = fma2g(k2[2 * j + 1], q2[2 * j + 1], c2);
        }
        float x0, x1, y0, y1;
        unpack2(a1, x0, x1); unpack2(a2, y0, y1);
        float r1 = (x0 + y0) + (x1 + y1);
        unpack2(b1, x0, x1); unpack2(b2, y0, y1);
        float r2 = (x0 + y0) + (x1 + y1);
        unpack2(c1, x0, x1); unpack2(c2, y0, y1);
        float kq = (x0 + y0) + (x1 + y1);

        r1 += __shfl_xor_sync(0xffffffffu, r1, 1);
        r1 += __shfl_xor_sync(0xffffffffu, r1, 2);
        r2 += __shfl_xor_sync(0xffffffffu, r2, 1);
        r2 += __shfl_xor_sync(0xffffffffu, r2, 2);
        kq += __shfl_xor_sync(0xffffffffu, kq, 1);
        kq += __shfl_xor_sync(0xffffffffu, kq, 2);

        const float z = fmaf(da, r1, ax + ba);
        const float e = __expf(-z);
        const float alpha = __fdividef(1.0f, 1.0f + e);
        const float w = fmaf(-vv, alpha, vv);            // (1-alpha)*v

        const ull alpha2 = pack2(alpha, alpha);
        const ull w2 = pack2(w, w);
        #pragma unroll
        for (int j = 0; j < 8; j++)
            S2[j] = fma2g(alpha2, S2[j], mul2(w2, k2[j]));

        if (c == 0) {
            const float o = fmaf(alpha, r2, w * kq);
            const float eo = __expf(-o);
            out[((size_t)t * BATCH + b) * NDIM + row] =
                o * o * __fdividef(1.0f, 1.0f + eo);
        }
    }

    if (Sfinal != nullptr) {
        float* sp = Sfinal + ((size_t)b * NDIM + row) * NDIM + c * 16;
        #pragma unroll
        for (int j = 0; j < 4; j++) {
            float lo0, hi0, lo1, hi1;
            unpack2(S2[2 * j], lo0, hi0);
            unpack2(S2[2 * j + 1], lo1, hi1);
            *(float4*)(sp + 4 * j) = make_float4(lo0, hi0, lo1, hi1);
        }
    }
}

// ---------------- launch ----------------
extern "C" void kernel_launch(void* const* d_in, const int* in_sizes, int n_in,
                              void* d_out, int out_size) {
    const float* x  = (const float*)d_in[0];
    const float* S0 = (const float*)d_in[1];
    const float* Wk = (const float*)d_in[2];
    const float* Wv = (const float*)d_in[3];
    const float* Wq = (const float*)d_in[4];
    const float* Wa = (const float*)d_in[5];
    const float* da = (const float*)d_in[6];
    const float* ba = (const float*)d_in[7];

    float* out = (float*)d_out;
    const int out_elems = T_STEPS * BATCH * NDIM;
    const int sf_elems  = BATCH * NDIM * NDIM;
    float* Sf = (out_size >= out_elems + sf_elems) ? (out + out_elems) : nullptr;

    const int smem_bytes = NSTAGE * STAGE_ELE * 2;   // 122880
    cudaFuncSetAttribute(gemm_mma, cudaFuncAttributeMaxDynamicSharedMemorySize, smem_bytes);

    convert_x<<<2048, 256>>>(x);
    convert_w<<<NTOT, 256>>>(Wk, Wv, Wq, Wa);

    dim3 ggrid(NTOT / BN, MROWS / BM);   // (2, 256)
    gemm_mma<<<ggrid, 256, smem_bytes>>>(0);

    recur_w<<<BATCH * 8, 32>>>(S0, da, ba, out, Sf);
}

// round 6
// speedup vs baseline: 2.5417x; 1.8539x over previous
#include <cuda_runtime.h>
#include <cuda_bf16.h>
#include <cstdint>

#define T_STEPS 2048
#define BATCH   16
#define DIM     1024
#define NDIM    64
#define NTOT    256
#define MROWS   (T_STEPS * BATCH)   // 32768

// ---------------- static device scratch ----------------
__device__ __nv_bfloat16 g_Ah[MROWS * DIM];
__device__ __nv_bfloat16 g_Al[MROWS * DIM];
__device__ __nv_bfloat16 g_Bh[NTOT * DIM];    // [n][k]
__device__ __nv_bfloat16 g_Bl[NTOT * DIM];
__device__ float g_P[MROWS * NTOT];           // [t*B+b][k|v|q|a]

// ---------------- PTX helpers (baseline ISA only) ----------------
__device__ __forceinline__ uint32_t smem_u32(const void* p) {
    return (uint32_t)__cvta_generic_to_shared(p);
}
__device__ __forceinline__ void cpa16(uint32_t sa, const void* g) {
    asm volatile("cp.async.cg.shared.global [%0], [%1], 16;" :: "r"(sa), "l"(g) : "memory");
}
__device__ __forceinline__ void cp_commit() {
    asm volatile("cp.async.commit_group;" ::: "memory");
}
template<int N>
__device__ __forceinline__ void cp_wait() {
    asm volatile("cp.async.wait_group %0;" :: "n"(N) : "memory");
}
__device__ __forceinline__ void ldm_x4(uint32_t& r0, uint32_t& r1, uint32_t& r2, uint32_t& r3,
                                       uint32_t addr) {
    asm volatile("ldmatrix.sync.aligned.m8n8.x4.shared.b16 {%0,%1,%2,%3}, [%4];"
                 : "=r"(r0), "=r"(r1), "=r"(r2), "=r"(r3) : "r"(addr));
}
__device__ __forceinline__ void mma_bf16(float* c, const uint32_t* a, const uint32_t* b) {
    asm volatile("mma.sync.aligned.m16n8k16.row.col.f32.bf16.bf16.f32 "
                 "{%0,%1,%2,%3}, {%4,%5,%6,%7}, {%8,%9}, {%0,%1,%2,%3};"
                 : "+f"(c[0]), "+f"(c[1]), "+f"(c[2]), "+f"(c[3])
                 : "r"(a[0]), "r"(a[1]), "r"(a[2]), "r"(a[3]), "r"(b[0]), "r"(b[1]));
}

// packed f32x2
typedef unsigned long long ull;
__device__ __forceinline__ ull pack2(float lo, float hi) {
    ull r; asm("mov.b64 %0, {%1, %2};" : "=l"(r) : "f"(lo), "f"(hi)); return r;
}
__device__ __forceinline__ void unpack2(ull v, float& lo, float& hi) {
    asm("mov.b64 {%0, %1}, %2;" : "=f"(lo), "=f"(hi) : "l"(v));
}
__device__ __forceinline__ ull fma2g(ull a, ull b, ull c) {
    ull d; asm("fma.rn.f32x2 %0, %1, %2, %3;" : "=l"(d) : "l"(a), "l"(b), "l"(c)); return d;
}
__device__ __forceinline__ ull mul2(ull a, ull b) {
    ull d; asm("mul.rn.f32x2 %0, %1, %2;" : "=l"(d) : "l"(a), "l"(b)); return d;
}

__device__ __forceinline__ void split_bf16(float x, __nv_bfloat16& h, __nv_bfloat16& l) {
    h = __float2bfloat16(x);
    l = __float2bfloat16(x - __bfloat162float(h));
}

// ---------------- prep kernels ----------------
__global__ void convert_x(const float* __restrict__ x) {
    const int total4 = MROWS * DIM / 4;
    for (int i = blockIdx.x * blockDim.x + threadIdx.x; i < total4;
         i += gridDim.x * blockDim.x) {
        float4 v = ((const float4*)x)[i];
        __nv_bfloat16 h0, h1, h2, h3, l0, l1, l2, l3;
        split_bf16(v.x, h0, l0); split_bf16(v.y, h1, l1);
        split_bf16(v.z, h2, l2); split_bf16(v.w, h3, l3);
        ((__nv_bfloat162*)g_Ah)[2 * i + 0] = __nv_bfloat162(h0, h1);
        ((__nv_bfloat162*)g_Ah)[2 * i + 1] = __nv_bfloat162(h2, h3);
        ((__nv_bfloat162*)g_Al)[2 * i + 0] = __nv_bfloat162(l0, l1);
        ((__nv_bfloat162*)g_Al)[2 * i + 1] = __nv_bfloat162(l2, l3);
    }
}

__global__ void convert_w(const float* __restrict__ Wk, const float* __restrict__ Wv,
                          const float* __restrict__ Wq, const float* __restrict__ Wa) {
    int n = blockIdx.x;
    int g = n >> 6, r = n & 63;
    const float* W = (g == 0) ? Wk : (g == 1) ? Wv : (g == 2) ? Wq : Wa;
    for (int d = threadIdx.x; d < DIM; d += blockDim.x) {
        __nv_bfloat16 h, l;
        split_bf16(W[r * DIM + d], h, l);
        g_Bh[n * DIM + d] = h;
        g_Bl[n * DIM + d] = l;
    }
}

// ---------------- mma.sync GEMM ----------------
#define BM 128
#define BN 128
#define BK 32
#define LDP 40
#define KT (DIM / BK)
#define NSTAGE 3
#define STAGE_ELE (4 * 128 * LDP)

__device__ __forceinline__ uint32_t soff(int stage, int arr, int row, int col) {
    return (uint32_t)(((stage * STAGE_ELE) + ((arr * 128 + row) * LDP) + col) * 2);
}

__global__ __launch_bounds__(256, 1) void gemm_mma(int unused) {
    extern __shared__ __nv_bfloat16 smem[];
    const uint32_t sbase = smem_u32(smem);

    const int m0 = blockIdx.y * BM;
    const int n0 = blockIdx.x * BN;
    const int tid = threadIdx.x;
    const int wid = tid >> 5;
    const int lane = tid & 31;
    const int warp_m = (wid & 3) * 32;
    const int warp_n = (wid >> 2) * 64;

    float acc[2][8][4];
    #pragma unroll
    for (int i = 0; i < 2; i++)
        #pragma unroll
        for (int j = 0; j < 8; j++)
            #pragma unroll
            for (int r = 0; r < 4; r++) acc[i][j][r] = 0.f;

    const int lm = lane >> 3;
    const int arow = (lm & 1) * 8 + (lane & 7);
    const int akc  = (lm >> 1) * 8;
    const int bnof = (lm >> 1) * 8 + (lane & 7);
    const int bkc  = (lm & 1) * 8;

    auto load_stage = [&](int stage, int kt) {
        const int k0 = kt * BK;
        #pragma unroll
        for (int arr = 0; arr < 4; arr++) {
            const __nv_bfloat16* gb = (arr == 0) ? g_Ah : (arr == 1) ? g_Al
                                   : (arr == 2) ? g_Bh : g_Bl;
            const int rbase = (arr < 2) ? m0 : n0;
            #pragma unroll
            for (int h = 0; h < 2; h++) {
                int cl = h * 256 + tid;
                int row = cl >> 2;
                int seg = cl & 3;
                cpa16(sbase + soff(stage, arr, row, seg * 8),
                      gb + (size_t)(rbase + row) * DIM + k0 + seg * 8);
            }
        }
        cp_commit();
    };

    load_stage(0, 0);
    load_stage(1, 1);

    int cur = 0;
    for (int kt = 0; kt < KT; ++kt) {
        if (kt + 2 < KT) {
            load_stage((kt + 2) % NSTAGE, kt + 2);
            cp_wait<2>();
        } else if (kt + 1 < KT) {
            cp_wait<1>();
        } else {
            cp_wait<0>();
        }
        __syncthreads();

        #pragma unroll
        for (int kk = 0; kk < BK; kk += 16) {
            uint32_t ah[2][4], al[2][4], bh[8][2], bl[8][2];
            #pragma unroll
            for (int mi = 0; mi < 2; mi++) {
                ldm_x4(ah[mi][0], ah[mi][1], ah[mi][2], ah[mi][3],
                       sbase + soff(cur, 0, warp_m + mi * 16 + arow, kk + akc));
                ldm_x4(al[mi][0], al[mi][1], al[mi][2], al[mi][3],
                       sbase + soff(cur, 1, warp_m + mi * 16 + arow, kk + akc));
            }
            #pragma unroll
            for (int p = 0; p < 4; p++) {
                ldm_x4(bh[2 * p][0], bh[2 * p][1], bh[2 * p + 1][0], bh[2 * p + 1][1],
                       sbase + soff(cur, 2, warp_n + p * 16 + bnof, kk + bkc));
                ldm_x4(bl[2 * p][0], bl[2 * p][1], bl[2 * p + 1][0], bl[2 * p + 1][1],
                       sbase + soff(cur, 3, warp_n + p * 16 + bnof, kk + bkc));
            }
            #pragma unroll
            for (int mi = 0; mi < 2; mi++)
                #pragma unroll
                for (int nb = 0; nb < 8; nb++) {
                    mma_bf16(acc[mi][nb], ah[mi], bh[nb]);
                    mma_bf16(acc[mi][nb], ah[mi], bl[nb]);
                    mma_bf16(acc[mi][nb], al[mi], bh[nb]);
                }
        }
        __syncthreads();
        cur = (cur + 1) % NSTAGE;
    }

    const int cr = lane >> 2;
    const int cc = (lane & 3) * 2;
    #pragma unroll
    for (int mi = 0; mi < 2; mi++) {
        #pragma unroll
        for (int nb = 0; nb < 8; nb++) {
            int row = m0 + warp_m + mi * 16 + cr;
            int col = n0 + warp_n + nb * 8 + cc;
            *(float2*)&g_P[(size_t)row * NTOT + col] =
                make_float2(acc[mi][nb][0], acc[mi][nb][1]);
            *(float2*)&g_P[(size_t)(row + 8) * NTOT + col] =
                make_float2(acc[mi][nb][2], acc[mi][nb][3]);
        }
    }
}

// ---------------- recurrence: deferred-reduction formulation ----------------
// r1_t = S_{t-1}.k_t = alpha_{t-1}*U_t + w_{t-1}*C_t,  U_t = S_{t-2}.k_t, C_t = k_{t-1}.k_t
// U,C computed one step early (off the serial chain). 4 rows/warp, 8 lanes/row.
#define RDEPTH 8

__device__ __forceinline__ float red8(float x) {
    x += __shfl_xor_sync(0xffffffffu, x, 1);
    x += __shfl_xor_sync(0xffffffffu, x, 2);
    x += __shfl_xor_sync(0xffffffffu, x, 4);
    return x;
}
__device__ __forceinline__ float dot4(const ull* a, const ull* b) {
    ull acc = 0;
    #pragma unroll
    for (int j = 0; j < 4; j++) acc = fma2g(a[j], b[j], acc);
    float lo, hi; unpack2(acc, lo, hi);
    return lo + hi;
}

__global__ __launch_bounds__(32, 1) void recur_w(const float* __restrict__ S0,
                                                 const float* __restrict__ dalpha,
                                                 const float* __restrict__ balpha,
                                                 float* __restrict__ out,
                                                 float* __restrict__ Sfinal) {
    const int b = blockIdx.x >> 4;           // batch
    const int rw = (blockIdx.x & 15) * 4;    // first row of this warp
    const int lane = threadIdx.x;
    const int row = rw + (lane >> 3);        // global row (0..63)
    const int c = lane & 7;                  // col chunk: cols [c*8, c*8+8)

    __shared__ __align__(16) float ring[RDEPTH][NTOT];

    ull S2[4];
    {
        const float* sp = S0 + ((size_t)b * NDIM + row) * NDIM + c * 8;
        float4 v0 = *(const float4*)(sp);
        float4 v1 = *(const float4*)(sp + 4);
        S2[0] = pack2(v0.x, v0.y); S2[1] = pack2(v0.z, v0.w);
        S2[2] = pack2(v1.x, v1.y); S2[3] = pack2(v1.z, v1.w);
    }
    const float da = dalpha[row];
    const float ba = balpha[row];

    // prime ring stages 0..6
    #pragma unroll
    for (int p = 0; p < 7; p++) {
        const float* gp = g_P + (size_t)(p * BATCH + b) * NTOT;
        uint32_t sa = smem_u32(&ring[p][lane * 8]);
        cpa16(sa, gp + lane * 8);
        cpa16(sa + 16, gp + lane * 8 + 4);
        cp_commit();
    }
    cp_wait<6>();
    __syncwarp();

    ull kc[4], qc[4];
    float vc, ac;
    {
        const float* kv = ring[0];
        float4 k0 = *(const float4*)&kv[c * 8];
        float4 k1 = *(const float4*)&kv[c * 8 + 4];
        float4 q0 = *(const float4*)&kv[2 * NDIM + c * 8];
        float4 q1 = *(const float4*)&kv[2 * NDIM + c * 8 + 4];
        kc[0] = pack2(k0.x, k0.y); kc[1] = pack2(k0.z, k0.w);
        kc[2] = pack2(k1.x, k1.y); kc[3] = pack2(k1.z, k1.w);
        qc[0] = pack2(q0.x, q0.y); qc[1] = pack2(q0.z, q0.w);
        qc[2] = pack2(q1.x, q1.y); qc[3] = pack2(q1.z, q1.w);
        vc = kv[NDIM + row];
        ac = kv[3 * NDIM + row];
    }

    float Uc = red8(dot4(S2, kc));   // S_init . k_0
    float Cc = 0.f;
    float alpha_p = 1.f, w_p = 0.f;

    for (int t = 0; t < T_STEPS; ++t) {
        cp_wait<5>();
        __syncwarp();

        // load next-step values (clamped at the end)
        const int tn = (t + 1 < T_STEPS) ? (t + 1) : t;
        const float* kv = ring[tn & (RDEPTH - 1)];
        ull kn[4], qn[4];
        {
            float4 k0 = *(const float4*)&kv[c * 8];
            float4 k1 = *(const float4*)&kv[c * 8 + 4];
            float4 q0 = *(const float4*)&kv[2 * NDIM + c * 8];
            float4 q1 = *(const float4*)&kv[2 * NDIM + c * 8 + 4];
            kn[0] = pack2(k0.x, k0.y); kn[1] = pack2(k0.z, k0.w);
            kn[2] = pack2(k1.x, k1.y); kn[3] = pack2(k1.z, k1.w);
            qn[0] = pack2(q0.x, q0.y); qn[1] = pack2(q0.z, q0.w);
            qn[2] = pack2(q1.x, q1.y); qn[3] = pack2(q1.z, q1.w);
        }
        const float vn = kv[NDIM + row];
        const float an = kv[3 * NDIM + row];

        // ---- serial scalar chain ----
        const float r1 = fmaf(alpha_p, Uc, w_p * Cc);
        const float z = fmaf(da, r1, ac + ba);
        const float e = __expf(-z);
        const float alpha = __fdividef(1.0f, 1.0f + e);
        const float w = fmaf(-vc, alpha, vc);        // (1-alpha)*v

        // ---- off-chain dots with pre-update S = S_{t-1} ----
        float Un = red8(dot4(S2, kn));     // S_{t-1}.k_{t+1}
        float Cn = red8(dot4(kc, kn));     // k_t.k_{t+1}
        float R2 = red8(dot4(S2, qc));     // S_{t-1}.q_t
        float E2 = red8(dot4(kc, qc));     // k_t.q_t

        // ---- S update ----
        const ull alpha2 = pack2(alpha, alpha);
        const ull w2 = pack2(w, w);
        #pragma unroll
        for (int j = 0; j < 4; j++)
            S2[j] = fma2g(alpha2, S2[j], mul2(w2, kc[j]));

        // ---- output (off-chain) ----
        if (c == 0) {
            const float o = fmaf(alpha, R2, w * E2);
            const float eo = __expf(-o);
            out[((size_t)t * BATCH + b) * NDIM + row] =
                o * o * __fdividef(1.0f, 1.0f + eo);
        }

        // ---- prefetch stage t+7 ----
        {
            const int tp = t + 7;
            if (tp < T_STEPS) {
                const float* gp = g_P + (size_t)(tp * BATCH + b) * NTOT;
                uint32_t sa = smem_u32(&ring[tp & (RDEPTH - 1)][lane * 8]);
                cpa16(sa, gp + lane * 8);
                cpa16(sa + 16, gp + lane * 8 + 4);
            }
            cp_commit();
        }

        // ---- rotate ----
        Uc = Un; Cc = Cn; alpha_p = alpha; w_p = w;
        #pragma unroll
        for (int j = 0; j < 4; j++) { kc[j] = kn[j]; qc[j] = qn[j]; }
        vc = vn; ac = an;
    }

    if (Sfinal != nullptr) {
        float* sp = Sfinal + ((size_t)b * NDIM + row) * NDIM + c * 8;
        float l0, h0, l1, h1;
        unpack2(S2[0], l0, h0); unpack2(S2[1], l1, h1);
        *(float4*)(sp) = make_float4(l0, h0, l1, h1);
        unpack2(S2[2], l0, h0); unpack2(S2[3], l1, h1);
        *(float4*)(sp + 4) = make_float4(l0, h0, l1, h1);
    }
}

// ---------------- launch ----------------
extern "C" void kernel_launch(void* const* d_in, const int* in_sizes, int n_in,
                              void* d_out, int out_size) {
    const float* x  = (const float*)d_in[0];
    const float* S0 = (const float*)d_in[1];
    const float* Wk = (const float*)d_in[2];
    const float* Wv = (const float*)d_in[3];
    const float* Wq = (const float*)d_in[4];
    const float* Wa = (const float*)d_in[5];
    const float* da = (const float*)d_in[6];
    const float* ba = (const float*)d_in[7];

    float* out = (float*)d_out;
    const int out_elems = T_STEPS * BATCH * NDIM;
    const int sf_elems  = BATCH * NDIM * NDIM;
    float* Sf = (out_size >= out_elems + sf_elems) ? (out + out_elems) : nullptr;

    const int smem_bytes = NSTAGE * STAGE_ELE * 2;   // 122880
    cudaFuncSetAttribute(gemm_mma, cudaFuncAttributeMaxDynamicSharedMemorySize, smem_bytes);

    convert_x<<<2048, 256>>>(x);
    convert_w<<<NTOT, 256>>>(Wk, Wv, Wq, Wa);

    dim3 ggrid(NTOT / BN, MROWS / BM);   // (2, 256)
    gemm_mma<<<ggrid, 256, smem_bytes>>>(0);

    recur_w<<<BATCH * 16, 32>>>(S0, da, ba, out, Sf);
}